// round 2
// baseline (speedup 1.0000x reference)
#include <cuda_runtime.h>

#define NEGV (-1e30f)

// ---------------- scratch (static device globals; no allocation) ----------------
static __device__ float g_px[33554432];   // [16*2048, 1024] relu(x@Wx^T)
static __device__ float g_py[33554432];   // [16*2048, 1024] relu(y@Wy^T)
static __device__ float g_s [67108864];   // [16, 2048, 2048] masked scores
static __device__ float g_rmax[32768];    // per (b,i) row max   (softmax axis=2)
static __device__ float g_rinv[32768];    // per (b,i) 1/rowsum
static __device__ float g_cmax[32768];    // per (b,j) col max   (softmax axis=1)
static __device__ float g_cinv[32768];    // per (b,j) 1/colsum
static __device__ int   g_mask_mode;      // 0=uint8, 1=int32, 2=float32

// ---------------- mask dtype detection -------------------------------------------
__global__ void detect_mask_kernel(const unsigned char* __restrict__ xm)
{
    if (threadIdx.x == 0 && blockIdx.x == 0) {
        unsigned int c1 = 0, c3 = 0;
        for (int k = 0; k < 4096; k += 4) { c1 |= xm[k + 1]; c3 |= xm[k + 3]; }
        g_mask_mode = c1 ? 0 : (c3 ? 2 : 1);
    }
}

__device__ __forceinline__ bool mask_at(const void* p, int idx, int mode)
{
    if (mode == 0) return ((const unsigned char*)p)[idx] != 0;
    if (mode == 1) return ((const int*)p)[idx] != 0;
    return ((const float*)p)[idx] != 0.0f;
}

// =================================================================================
// Tile config shared by all GEMM kernels: BM=BN=128, BK=8, 256 threads, 8x8/thread
// =================================================================================

// ---------------- projections: P = relu(X[M,1024] @ W[1024,1024]^T) --------------
__global__ __launch_bounds__(256, 2)
void proj_kernel(const float* __restrict__ X, const float* __restrict__ W, int which)
{
    float* __restrict__ P = which ? g_py : g_px;
    __shared__ float As[8][132];
    __shared__ float Bs[8][132];
    const int tid = threadIdx.x;
    const int bm = blockIdx.y * 128;
    const int bn = blockIdx.x * 128;
    const int m0 = (tid >> 4) * 8;
    const int n0 = (tid & 15) * 8;
    const int lr = tid >> 1;
    const int lc = (tid & 1) * 4;

    float acc[8][8];
#pragma unroll
    for (int i = 0; i < 8; i++)
#pragma unroll
        for (int j = 0; j < 8; j++) acc[i][j] = 0.0f;

    const float* ap = X + (size_t)(bm + lr) * 1024 + lc;
    const float* bp = W + (size_t)(bn + lr) * 1024 + lc;

    for (int kt = 0; kt < 1024; kt += 8) {
        float4 av = *reinterpret_cast<const float4*>(ap + kt);
        float4 bv = *reinterpret_cast<const float4*>(bp + kt);
        As[lc + 0][lr] = av.x; As[lc + 1][lr] = av.y; As[lc + 2][lr] = av.z; As[lc + 3][lr] = av.w;
        Bs[lc + 0][lr] = bv.x; Bs[lc + 1][lr] = bv.y; Bs[lc + 2][lr] = bv.z; Bs[lc + 3][lr] = bv.w;
        __syncthreads();
#pragma unroll
        for (int k = 0; k < 8; k++) {
            float a[8], b[8];
            *reinterpret_cast<float4*>(&a[0]) = *reinterpret_cast<const float4*>(&As[k][m0]);
            *reinterpret_cast<float4*>(&a[4]) = *reinterpret_cast<const float4*>(&As[k][m0 + 4]);
            *reinterpret_cast<float4*>(&b[0]) = *reinterpret_cast<const float4*>(&Bs[k][n0]);
            *reinterpret_cast<float4*>(&b[4]) = *reinterpret_cast<const float4*>(&Bs[k][n0 + 4]);
#pragma unroll
            for (int i = 0; i < 8; i++)
#pragma unroll
                for (int j = 0; j < 8; j++)
                    acc[i][j] = fmaf(a[i], b[j], acc[i][j]);
        }
        __syncthreads();
    }
#pragma unroll
    for (int i = 0; i < 8; i++) {
        float* cp = P + (size_t)(bm + m0 + i) * 1024 + bn + n0;
        float4 o;
        o.x = fmaxf(acc[i][0], 0.f); o.y = fmaxf(acc[i][1], 0.f);
        o.z = fmaxf(acc[i][2], 0.f); o.w = fmaxf(acc[i][3], 0.f);
        *reinterpret_cast<float4*>(cp) = o;
        o.x = fmaxf(acc[i][4], 0.f); o.y = fmaxf(acc[i][5], 0.f);
        o.z = fmaxf(acc[i][6], 0.f); o.w = fmaxf(acc[i][7], 0.f);
        *reinterpret_cast<float4*>(cp + 4) = o;
    }
}

// ---------------- scores: s[b,i,j] = px[b,i,:]·py[b,j,:], masked ------------------
__global__ __launch_bounds__(256, 2)
void score_kernel(const void* __restrict__ XM, const void* __restrict__ YM)
{
    const int b = blockIdx.z;
    const float* __restrict__ A = g_px + (size_t)b * 2048 * 1024;
    const float* __restrict__ Bm = g_py + (size_t)b * 2048 * 1024;
    float* __restrict__ C = g_s + (size_t)b * 2048 * 2048;

    __shared__ float As[8][132];
    __shared__ float Bs[8][132];
    const int tid = threadIdx.x;
    const int bm = blockIdx.y * 128;
    const int bn = blockIdx.x * 128;
    const int m0 = (tid >> 4) * 8;
    const int n0 = (tid & 15) * 8;
    const int lr = tid >> 1;
    const int lc = (tid & 1) * 4;
    const int mode = g_mask_mode;

    float acc[8][8];
#pragma unroll
    for (int i = 0; i < 8; i++)
#pragma unroll
        for (int j = 0; j < 8; j++) acc[i][j] = 0.0f;

    const float* ap = A + (size_t)(bm + lr) * 1024 + lc;
    const float* bp = Bm + (size_t)(bn + lr) * 1024 + lc;

    for (int kt = 0; kt < 1024; kt += 8) {
        float4 av = *reinterpret_cast<const float4*>(ap + kt);
        float4 bv = *reinterpret_cast<const float4*>(bp + kt);
        As[lc + 0][lr] = av.x; As[lc + 1][lr] = av.y; As[lc + 2][lr] = av.z; As[lc + 3][lr] = av.w;
        Bs[lc + 0][lr] = bv.x; Bs[lc + 1][lr] = bv.y; Bs[lc + 2][lr] = bv.z; Bs[lc + 3][lr] = bv.w;
        __syncthreads();
#pragma unroll
        for (int k = 0; k < 8; k++) {
            float a[8], b2[8];
            *reinterpret_cast<float4*>(&a[0])  = *reinterpret_cast<const float4*>(&As[k][m0]);
            *reinterpret_cast<float4*>(&a[4])  = *reinterpret_cast<const float4*>(&As[k][m0 + 4]);
            *reinterpret_cast<float4*>(&b2[0]) = *reinterpret_cast<const float4*>(&Bs[k][n0]);
            *reinterpret_cast<float4*>(&b2[4]) = *reinterpret_cast<const float4*>(&Bs[k][n0 + 4]);
#pragma unroll
            for (int i = 0; i < 8; i++)
#pragma unroll
                for (int j = 0; j < 8; j++)
                    acc[i][j] = fmaf(a[i], b2[j], acc[i][j]);
        }
        __syncthreads();
    }

    bool ymv[8];
#pragma unroll
    for (int j = 0; j < 8; j++) ymv[j] = mask_at(YM, b * 2048 + bn + n0 + j, mode);

#pragma unroll
    for (int i = 0; i < 8; i++) {
        const bool mi = mask_at(XM, b * 2048 + bm + m0 + i, mode);
        float* cp = C + (size_t)(bm + m0 + i) * 2048 + bn + n0;
        float4 o;
        o.x = (mi || ymv[0]) ? NEGV : acc[i][0];
        o.y = (mi || ymv[1]) ? NEGV : acc[i][1];
        o.z = (mi || ymv[2]) ? NEGV : acc[i][2];
        o.w = (mi || ymv[3]) ? NEGV : acc[i][3];
        *reinterpret_cast<float4*>(cp) = o;
        o.x = (mi || ymv[4]) ? NEGV : acc[i][4];
        o.y = (mi || ymv[5]) ? NEGV : acc[i][5];
        o.z = (mi || ymv[6]) ? NEGV : acc[i][6];
        o.w = (mi || ymv[7]) ? NEGV : acc[i][7];
        *reinterpret_cast<float4*>(cp + 4) = o;
    }
}

// ---------------- per-row softmax stats (axis=2) ----------------------------------
__global__ void row_stats_kernel()
{
    const int row = blockIdx.x;                      // b*2048 + i
    const float* sp = g_s + (size_t)row * 2048;
    const int t = threadIdx.x;                       // 256
    float v[8];
#pragma unroll
    for (int r = 0; r < 8; r++) v[r] = sp[t + 256 * r];
    float m = v[0];
#pragma unroll
    for (int r = 1; r < 8; r++) m = fmaxf(m, v[r]);
    __shared__ float red[256];
    red[t] = m;
    __syncthreads();
    for (int s = 128; s > 0; s >>= 1) {
        if (t < s) red[t] = fmaxf(red[t], red[t + s]);
        __syncthreads();
    }
    const float rm = red[0];
    __syncthreads();
    float sum = 0.f;
#pragma unroll
    for (int r = 0; r < 8; r++) sum += __expf(v[r] - rm);
    red[t] = sum;
    __syncthreads();
    for (int s = 128; s > 0; s >>= 1) {
        if (t < s) red[t] += red[t + s];
        __syncthreads();
    }
    if (t == 0) { g_rmax[row] = rm; g_rinv[row] = 1.0f / red[0]; }
}

// ---------------- per-column softmax stats (axis=1) -------------------------------
__global__ void col_stats_kernel()
{
    const int b  = blockIdx.y;
    const int tx = threadIdx.x;                      // 32
    const int ty = threadIdx.y;                      // 8
    const int j  = blockIdx.x * 32 + tx;
    const float* sp = g_s + (size_t)b * 2048 * 2048 + j;

    float m = -3e38f;
    for (int i = ty; i < 2048; i += 8) m = fmaxf(m, sp[(size_t)i * 2048]);
    __shared__ float red[8][32];
    red[ty][tx] = m;
    __syncthreads();
    if (ty == 0) {
        float mm = red[0][tx];
#pragma unroll
        for (int r = 1; r < 8; r++) mm = fmaxf(mm, red[r][tx]);
        red[0][tx] = mm;
    }
    __syncthreads();
    const float cm = red[0][tx];
    __syncthreads();
    float sum = 0.f;
    for (int i = ty; i < 2048; i += 8) sum += __expf(sp[(size_t)i * 2048] - cm);
    red[ty][tx] = sum;
    __syncthreads();
    if (ty == 0) {
        float ss = red[0][tx];
#pragma unroll
        for (int r = 1; r < 8; r++) ss += red[r][tx];
        g_cmax[b * 2048 + j] = cm;
        g_cinv[b * 2048 + j] = 1.0f / ss;
    }
}

// ---------------- y_h[b,i,d] = sum_j softmax2(s)[i,j] * y[b,j,d] ------------------
__global__ __launch_bounds__(256, 2)
void attn_row_kernel(const float* __restrict__ Y, float* __restrict__ Out)
{
    const int b = blockIdx.z;
    const float* __restrict__ S  = g_s + (size_t)b * 2048 * 2048;
    const float* __restrict__ Bv = Y + (size_t)b * 2048 * 1024;
    float* __restrict__ C = Out + (size_t)b * 2048 * 1024;

    __shared__ float As[8][132];
    __shared__ float Bs[8][132];
    const int tid = threadIdx.x;
    const int bm = blockIdx.y * 128;
    const int bn = blockIdx.x * 128;
    const int m0 = (tid >> 4) * 8;
    const int n0 = (tid & 15) * 8;
    const int lr = tid >> 1;
    const int lc = (tid & 1) * 4;
    const int bk  = tid >> 5;
    const int bn4 = (tid & 31) * 4;

    const float rm = g_rmax[b * 2048 + bm + lr];
    const float ri = g_rinv[b * 2048 + bm + lr];

    float acc[8][8];
#pragma unroll
    for (int i = 0; i < 8; i++)
#pragma unroll
        for (int j = 0; j < 8; j++) acc[i][j] = 0.0f;

    const float* ap = S + (size_t)(bm + lr) * 2048 + lc;
    const float* bp = Bv + (size_t)bk * 1024 + bn + bn4;

    for (int kt = 0; kt < 2048; kt += 8) {
        float4 av = *reinterpret_cast<const float4*>(ap + kt);
        As[lc + 0][lr] = __expf(av.x - rm) * ri;
        As[lc + 1][lr] = __expf(av.y - rm) * ri;
        As[lc + 2][lr] = __expf(av.z - rm) * ri;
        As[lc + 3][lr] = __expf(av.w - rm) * ri;
        float4 bv4 = *reinterpret_cast<const float4*>(bp + (size_t)kt * 1024);
        *reinterpret_cast<float4*>(&Bs[bk][bn4]) = bv4;
        __syncthreads();
#pragma unroll
        for (int k = 0; k < 8; k++) {
            float a[8], b2[8];
            *reinterpret_cast<float4*>(&a[0])  = *reinterpret_cast<const float4*>(&As[k][m0]);
            *reinterpret_cast<float4*>(&a[4])  = *reinterpret_cast<const float4*>(&As[k][m0 + 4]);
            *reinterpret_cast<float4*>(&b2[0]) = *reinterpret_cast<const float4*>(&Bs[k][n0]);
            *reinterpret_cast<float4*>(&b2[4]) = *reinterpret_cast<const float4*>(&Bs[k][n0 + 4]);
#pragma unroll
            for (int i = 0; i < 8; i++)
#pragma unroll
                for (int j = 0; j < 8; j++)
                    acc[i][j] = fmaf(a[i], b2[j], acc[i][j]);
        }
        __syncthreads();
    }
#pragma unroll
    for (int i = 0; i < 8; i++) {
        float* cp = C + (size_t)(bm + m0 + i) * 1024 + bn + n0;
        *reinterpret_cast<float4*>(cp)     = *reinterpret_cast<float4*>(&acc[i][0]);
        *reinterpret_cast<float4*>(cp + 4) = *reinterpret_cast<float4*>(&acc[i][4]);
    }
}

// ---------------- x_h[b,j,d] = sum_i softmax1(s)[i,j] * x[b,i,d] ------------------
__global__ __launch_bounds__(256, 2)
void attn_col_kernel(const float* __restrict__ X, float* __restrict__ Out)
{
    const int b = blockIdx.z;
    const float* __restrict__ S  = g_s + (size_t)b * 2048 * 2048;
    const float* __restrict__ Bv = X + (size_t)b * 2048 * 1024;
    float* __restrict__ C = Out + (size_t)b * 2048 * 1024;

    __shared__ float As[8][132];
    __shared__ float Bs[8][132];
    const int tid = threadIdx.x;
    const int bm = blockIdx.y * 128;   // j tile
    const int bn = blockIdx.x * 128;   // d tile
    const int m0 = (tid >> 4) * 8;
    const int n0 = (tid & 15) * 8;
    const int ak = tid >> 5;
    const int am = (tid & 31) * 4;

    float cm[4], ci[4];
#pragma unroll
    for (int l = 0; l < 4; l++) {
        cm[l] = g_cmax[b * 2048 + bm + am + l];
        ci[l] = g_cinv[b * 2048 + bm + am + l];
    }

    float acc[8][8];
#pragma unroll
    for (int i = 0; i < 8; i++)
#pragma unroll
        for (int j = 0; j < 8; j++) acc[i][j] = 0.0f;

    const float* ap = S + (size_t)ak * 2048 + bm + am;
    const float* bp = Bv + (size_t)ak * 1024 + bn + am;

    for (int kt = 0; kt < 2048; kt += 8) {
        float4 av = *reinterpret_cast<const float4*>(ap + (size_t)kt * 2048);
        float4 t;
        t.x = __expf(av.x - cm[0]) * ci[0];
        t.y = __expf(av.y - cm[1]) * ci[1];
        t.z = __expf(av.z - cm[2]) * ci[2];
        t.w = __expf(av.w - cm[3]) * ci[3];
        *reinterpret_cast<float4*>(&As[ak][am]) = t;
        float4 bv4 = *reinterpret_cast<const float4*>(bp + (size_t)kt * 1024);
        *reinterpret_cast<float4*>(&Bs[ak][am]) = bv4;
        __syncthreads();
#pragma unroll
        for (int k = 0; k < 8; k++) {
            float a[8], b2[8];
            *reinterpret_cast<float4*>(&a[0])  = *reinterpret_cast<const float4*>(&As[k][m0]);
            *reinterpret_cast<float4*>(&a[4])  = *reinterpret_cast<const float4*>(&As[k][m0 + 4]);
            *reinterpret_cast<float4*>(&b2[0]) = *reinterpret_cast<const float4*>(&Bs[k][n0]);
            *reinterpret_cast<float4*>(&b2[4]) = *reinterpret_cast<const float4*>(&Bs[k][n0 + 4]);
#pragma unroll
            for (int i = 0; i < 8; i++)
#pragma unroll
                for (int j = 0; j < 8; j++)
                    acc[i][j] = fmaf(a[i], b2[j], acc[i][j]);
        }
        __syncthreads();
    }
#pragma unroll
    for (int i = 0; i < 8; i++) {
        float* cp = C + (size_t)(bm + m0 + i) * 1024 + bn + n0;
        *reinterpret_cast<float4*>(cp)     = *reinterpret_cast<float4*>(&acc[i][0]);
        *reinterpret_cast<float4*>(cp + 4) = *reinterpret_cast<float4*>(&acc[i][4]);
    }
}

// =================================================================================
extern "C" void kernel_launch(void* const* d_in, const int* in_sizes, int n_in,
                              void* d_out, int out_size)
{
    (void)in_sizes; (void)n_in; (void)out_size;
    const float* x  = (const float*)d_in[0];
    const float* y  = (const float*)d_in[1];
    const void*  xm = d_in[2];
    const void*  ym = d_in[3];
    const float* Wx = (const float*)d_in[4];
    const float* Wy = (const float*)d_in[5];
    float* out = (float*)d_out;

    // detect mask dtype (bool-as-uint8 / int32 / float32)
    detect_mask_kernel<<<1, 32>>>((const unsigned char*)xm);
    // px = relu(x @ Wx^T), py = relu(y @ Wy^T)
    proj_kernel<<<dim3(8, 256), 256>>>(x, Wx, 0);
    proj_kernel<<<dim3(8, 256), 256>>>(y, Wy, 1);
    // s = px @ py^T (+ mask)
    score_kernel<<<dim3(16, 16, 16), 256>>>(xm, ym);
    // softmax stats both directions
    row_stats_kernel<<<32768, 256>>>();
    col_stats_kernel<<<dim3(64, 16), dim3(32, 8)>>>();
    // y_h = softmax(s, axis=2) @ y ; x_h = softmax(s, axis=1)^T @ x
    attn_row_kernel<<<dim3(8, 16, 16), 256>>>(y, out);
    attn_col_kernel<<<dim3(8, 16, 16), 256>>>(x, out + 33554432);
}

// round 4
// speedup vs baseline: 1.7115x; 1.7115x over previous
#include <cuda_runtime.h>
#include <cuda_bf16.h>
#include <cstdint>

#define NEGV (-1e30f)

// ============================ scratch (device globals) ============================
static __device__ __nv_bfloat16 g_xhi[33554432], g_xlo[33554432];   // x split [16*2048,1024]
static __device__ __nv_bfloat16 g_yhi[33554432], g_ylo[33554432];   // y split
static __device__ __nv_bfloat16 g_wxhi[1048576], g_wxlo[1048576];   // Wx split [1024,1024]
static __device__ __nv_bfloat16 g_wyhi[1048576], g_wylo[1048576];
static __device__ __nv_bfloat16 g_pxhi[33554432], g_pxlo[33554432]; // relu proj splits
static __device__ __nv_bfloat16 g_pyhi[33554432], g_pylo[33554432];
static __device__ float         g_s[67108864];                      // [16,2048,2048] masked scores
static __device__ __nv_bfloat16 g_Phi[67108864], g_Plo[67108864];   // row-softmax probs [i,j]
static __device__ __nv_bfloat16 g_Pchi[67108864], g_Pclo[67108864]; // col-softmax probs transposed [j,i]
static __device__ __nv_bfloat16 g_yThi[33554432], g_yTlo[33554432]; // y^T [d,j]
static __device__ __nv_bfloat16 g_xThi[33554432], g_xTlo[33554432]; // x^T [d,i]
static __device__ float g_rmax[32768], g_rinv[32768];
static __device__ float g_cmax[32768], g_cinv[32768];
static __device__ int   g_mask_mode;

// ============================ helpers =============================================
static __device__ __forceinline__ uint32_t smem_u32(const void* p) {
    uint32_t a;
    asm("{ .reg .u64 t; cvta.to.shared.u64 t, %1; cvt.u32.u64 %0, t; }" : "=r"(a) : "l"(p));
    return a;
}

#define LDSM4(R, A)                                                                   \
    asm volatile("ldmatrix.sync.aligned.m8n8.x4.shared.b16 {%0,%1,%2,%3}, [%4];"      \
        : "=r"((R)[0]), "=r"((R)[1]), "=r"((R)[2]), "=r"((R)[3]) : "r"(A))

#define MMA_BF16(C, A, B0, B1)                                                        \
    asm volatile("mma.sync.aligned.m16n8k16.row.col.f32.bf16.bf16.f32 "               \
        "{%0,%1,%2,%3},{%4,%5,%6,%7},{%8,%9},{%0,%1,%2,%3};"                          \
        : "+f"((C)[0]), "+f"((C)[1]), "+f"((C)[2]), "+f"((C)[3])                      \
        : "r"((A)[0]), "r"((A)[1]), "r"((A)[2]), "r"((A)[3]), "r"(B0), "r"(B1))

__global__ void detect_mask_kernel(const unsigned char* __restrict__ xm) {
    if (threadIdx.x == 0 && blockIdx.x == 0) {
        unsigned int c1 = 0, c3 = 0;
        for (int k = 0; k < 4096; k += 4) { c1 |= xm[k + 1]; c3 |= xm[k + 3]; }
        g_mask_mode = c1 ? 0 : (c3 ? 2 : 1);
    }
}
__device__ __forceinline__ bool mask_at(const void* p, int idx, int mode) {
    if (mode == 0) return ((const unsigned char*)p)[idx] != 0;
    if (mode == 1) return ((const int*)p)[idx] != 0;
    return ((const float*)p)[idx] != 0.0f;
}

__device__ __forceinline__ void split2(float v, __nv_bfloat16& h, __nv_bfloat16& l) {
    h = __float2bfloat16(v);
    l = __float2bfloat16(v - __bfloat162float(h));
}

// ============================ split / transpose kernels ===========================
__global__ void split_plain_kernel(const float* __restrict__ src, int which, int n) {
    __nv_bfloat16 *H, *L;
    if (which == 0)      { H = g_xhi;  L = g_xlo;  }
    else if (which == 1) { H = g_yhi;  L = g_ylo;  }
    else if (which == 2) { H = g_wxhi; L = g_wxlo; }
    else                 { H = g_wyhi; L = g_wylo; }
    int i4 = (blockIdx.x * 256 + threadIdx.x) * 4;
    if (i4 >= n) return;
    float4 v = *reinterpret_cast<const float4*>(src + i4);
    __nv_bfloat16 h0, l0, h1, l1, h2, l2, h3, l3;
    split2(v.x, h0, l0); split2(v.y, h1, l1); split2(v.z, h2, l2); split2(v.w, h3, l3);
    ushort4 Hp = { __bfloat16_as_ushort(h0), __bfloat16_as_ushort(h1),
                   __bfloat16_as_ushort(h2), __bfloat16_as_ushort(h3) };
    ushort4 Lp = { __bfloat16_as_ushort(l0), __bfloat16_as_ushort(l1),
                   __bfloat16_as_ushort(l2), __bfloat16_as_ushort(l3) };
    *reinterpret_cast<ushort4*>(H + i4) = Hp;
    *reinterpret_cast<ushort4*>(L + i4) = Lp;
}

// src [b][2048 r][1024 c] fp32 -> dst [b][1024 c][2048 r] bf16 hi/lo
__global__ void transpose_split_kernel(const float* __restrict__ src, int which) {
    __nv_bfloat16* H = which ? g_xThi : g_yThi;
    __nv_bfloat16* L = which ? g_xTlo : g_yTlo;
    __shared__ float sm[32][33];
    const int b = blockIdx.z;
    const int c0 = blockIdx.x * 32, r0 = blockIdx.y * 32;
    const int tx = threadIdx.x, ty = threadIdx.y;
    const float* S = src + (size_t)b * 2048 * 1024;
#pragma unroll
    for (int k = 0; k < 4; k++) {
        int r = ty * 4 + k;
        sm[r][tx] = S[(size_t)(r0 + r) * 1024 + c0 + tx];
    }
    __syncthreads();
    __nv_bfloat16* Hb = H + (size_t)b * 1024 * 2048;
    __nv_bfloat16* Lb = L + (size_t)b * 1024 * 2048;
#pragma unroll
    for (int k = 0; k < 4; k++) {
        int c = ty * 4 + k;
        float v = sm[tx][c];
        __nv_bfloat16 h, l; split2(v, h, l);
        size_t o = (size_t)(c0 + c) * 2048 + r0 + tx;
        Hb[o] = h; Lb[o] = l;
    }
}

// ============================ softmax stats =======================================
__global__ void row_stats_kernel() {
    const int row = blockIdx.x;
    const float* sp = g_s + (size_t)row * 2048;
    const int t = threadIdx.x;
    float v[8];
#pragma unroll
    for (int r = 0; r < 8; r++) v[r] = sp[t + 256 * r];
    float m = v[0];
#pragma unroll
    for (int r = 1; r < 8; r++) m = fmaxf(m, v[r]);
    __shared__ float red[256];
    red[t] = m; __syncthreads();
    for (int s = 128; s > 0; s >>= 1) { if (t < s) red[t] = fmaxf(red[t], red[t + s]); __syncthreads(); }
    const float rm = red[0]; __syncthreads();
    float sum = 0.f;
#pragma unroll
    for (int r = 0; r < 8; r++) sum += __expf(v[r] - rm);
    red[t] = sum; __syncthreads();
    for (int s = 128; s > 0; s >>= 1) { if (t < s) red[t] += red[t + s]; __syncthreads(); }
    if (t == 0) { g_rmax[row] = rm; g_rinv[row] = 1.0f / red[0]; }
}

__global__ void col_stats_kernel() {
    const int b = blockIdx.y;
    const int tx = threadIdx.x, ty = threadIdx.y;
    const int j = blockIdx.x * 32 + tx;
    const float* sp = g_s + (size_t)b * 2048 * 2048 + j;
    float m = -3e38f;
    for (int i = ty; i < 2048; i += 8) m = fmaxf(m, sp[(size_t)i * 2048]);
    __shared__ float red[8][32];
    red[ty][tx] = m; __syncthreads();
    if (ty == 0) {
        float mm = red[0][tx];
#pragma unroll
        for (int r = 1; r < 8; r++) mm = fmaxf(mm, red[r][tx]);
        red[0][tx] = mm;
    }
    __syncthreads();
    const float cm = red[0][tx]; __syncthreads();
    float sum = 0.f;
    for (int i = ty; i < 2048; i += 8) sum += __expf(sp[(size_t)i * 2048] - cm);
    red[ty][tx] = sum; __syncthreads();
    if (ty == 0) {
        float ss = red[0][tx];
#pragma unroll
        for (int r = 1; r < 8; r++) ss += red[r][tx];
        g_cmax[b * 2048 + j] = cm;
        g_cinv[b * 2048 + j] = 1.0f / ss;
    }
}

// ============================ exp + split kernels =================================
__global__ void exp_row_kernel() {
    size_t i4 = ((size_t)blockIdx.x * 256 + threadIdx.x) * 4;
    int row = (int)(i4 >> 11);
    float rm = g_rmax[row], ri = g_rinv[row];
    float4 v = *reinterpret_cast<const float4*>(g_s + i4);
    float p0 = __expf(v.x - rm) * ri, p1 = __expf(v.y - rm) * ri;
    float p2 = __expf(v.z - rm) * ri, p3 = __expf(v.w - rm) * ri;
    __nv_bfloat16 h0, l0, h1, l1, h2, l2, h3, l3;
    split2(p0, h0, l0); split2(p1, h1, l1); split2(p2, h2, l2); split2(p3, h3, l3);
    ushort4 Hp = { __bfloat16_as_ushort(h0), __bfloat16_as_ushort(h1),
                   __bfloat16_as_ushort(h2), __bfloat16_as_ushort(h3) };
    ushort4 Lp = { __bfloat16_as_ushort(l0), __bfloat16_as_ushort(l1),
                   __bfloat16_as_ushort(l2), __bfloat16_as_ushort(l3) };
    *reinterpret_cast<ushort4*>(g_Phi + i4) = Hp;
    *reinterpret_cast<ushort4*>(g_Plo + i4) = Lp;
}

__global__ void exp_colT_kernel() {
    __shared__ float sm[32][33];
    const int b = blockIdx.z;
    const int i0 = blockIdx.x * 32, j0 = blockIdx.y * 32;
    const int tx = threadIdx.x, ty = threadIdx.y;
    const float* S = g_s + (size_t)b * 2048 * 2048;
    const int j = j0 + tx;
    const float cm = g_cmax[b * 2048 + j], ci = g_cinv[b * 2048 + j];
#pragma unroll
    for (int k = 0; k < 4; k++) {
        int i = ty * 4 + k;
        float v = S[(size_t)(i0 + i) * 2048 + j];
        sm[tx][i] = __expf(v - cm) * ci;
    }
    __syncthreads();
    __nv_bfloat16* Hb = g_Pchi + (size_t)b * 2048 * 2048;
    __nv_bfloat16* Lb = g_Pclo + (size_t)b * 2048 * 2048;
#pragma unroll
    for (int k = 0; k < 4; k++) {
        int jj = ty * 4 + k;
        float v = sm[jj][tx];
        __nv_bfloat16 h, l; split2(v, h, l);
        size_t o = (size_t)(j0 + jj) * 2048 + i0 + tx;
        Hb[o] = h; Lb[o] = l;
    }
}

// ============================ HMMA split GEMM =====================================
// which: 0=proj_x, 1=proj_y, 2=score, 3=attn_row, 4=attn_col
// CTA tile 128x128, 8 warps (4M x 2N), warp tile 32x64, K-chunk 32, double buffer.
// Smem per chunk: 4 tiles (Ahi,Alo,Bhi,Blo), each 128 rows x 80B (64B data + 16B pad).
__global__ __launch_bounds__(256, 2)
void gemm_hmma_kernel(int which, float* __restrict__ Cout,
                      const void* __restrict__ XM, const void* __restrict__ YM)
{
    const __nv_bfloat16 *Ah, *Al, *Bh, *Bl;
    size_t sAb = 0, sBb = 0, sCb = 0;
    int lda, ldb, K, ldc, mode;
    float* C = Cout;
    __nv_bfloat16 *Chi = nullptr, *Clo = nullptr;
    if (which == 0) {
        Ah = g_xhi; Al = g_xlo; Bh = g_wxhi; Bl = g_wxlo;
        lda = 1024; ldb = 1024; K = 1024; ldc = 1024; mode = 0;
        Chi = g_pxhi; Clo = g_pxlo;
    } else if (which == 1) {
        Ah = g_yhi; Al = g_ylo; Bh = g_wyhi; Bl = g_wylo;
        lda = 1024; ldb = 1024; K = 1024; ldc = 1024; mode = 0;
        Chi = g_pyhi; Clo = g_pylo;
    } else if (which == 2) {
        Ah = g_pxhi; Al = g_pxlo; Bh = g_pyhi; Bl = g_pylo;
        sAb = (size_t)2048 * 1024; sBb = (size_t)2048 * 1024; sCb = (size_t)2048 * 2048;
        lda = 1024; ldb = 1024; K = 1024; ldc = 2048; mode = 1;
        C = g_s;
    } else if (which == 3) {
        Ah = g_Phi; Al = g_Plo; Bh = g_yThi; Bl = g_yTlo;
        sAb = (size_t)2048 * 2048; sBb = (size_t)1024 * 2048; sCb = (size_t)2048 * 1024;
        lda = 2048; ldb = 2048; K = 2048; ldc = 1024; mode = 2;
    } else {
        Ah = g_Pchi; Al = g_Pclo; Bh = g_xThi; Bl = g_xTlo;
        sAb = (size_t)2048 * 2048; sBb = (size_t)1024 * 2048; sCb = (size_t)2048 * 1024;
        lda = 2048; ldb = 2048; K = 2048; ldc = 1024; mode = 2;
    }

    extern __shared__ __align__(16) char smem_raw[];
    const uint32_t sb = smem_u32(smem_raw);
    const int tid = threadIdx.x, wid = tid >> 5, lane = tid & 31;
    const int warp_m = wid & 3, warp_n = wid >> 2;
    const int b = blockIdx.z;
    const int m0 = blockIdx.y * 128, n0 = blockIdx.x * 128;

    const __nv_bfloat16* tp[4] = {
        Ah + (size_t)b * sAb + (size_t)m0 * lda,
        Al + (size_t)b * sAb + (size_t)m0 * lda,
        Bh + (size_t)b * sBb + (size_t)n0 * ldb,
        Bl + (size_t)b * sBb + (size_t)n0 * ldb
    };

    float acc[2][8][4];
#pragma unroll
    for (int i = 0; i < 2; i++)
#pragma unroll
        for (int j = 0; j < 8; j++)
#pragma unroll
            for (int q = 0; q < 4; q++) acc[i][j][q] = 0.0f;

    // per-lane ldmatrix offsets (bytes)
    const uint32_t aoff = (uint32_t)(warp_m * 32 + (lane & 7) + ((lane >> 3) & 1) * 8) * 80
                        + ((lane >> 4) & 1) * 16;
    const uint32_t boff = (uint32_t)(warp_n * 64 + (lane & 7) + (lane >> 4) * 8) * 80
                        + ((lane >> 3) & 1) * 16;

    const int NC = K >> 5;

    auto load_chunk = [&](int ch, int buf) {
#pragma unroll
        for (int i = 0; i < 8; i++) {
            const int o = i >> 1;
            const int idx = ((i & 1) << 8) + tid;
            const int row = idx >> 2, gr = idx & 3;
            const __nv_bfloat16* src = tp[o] + (size_t)row * (o < 2 ? lda : ldb) + ch * 32 + gr * 8;
            const uint32_t dst = sb + (uint32_t)buf * 40960 + (uint32_t)o * 10240
                               + (uint32_t)row * 80 + gr * 16;
            asm volatile("cp.async.cg.shared.global [%0], [%1], 16;" :: "r"(dst), "l"(src));
        }
        asm volatile("cp.async.commit_group;");
    };

    load_chunk(0, 0);
    for (int ch = 0; ch < NC; ch++) {
        if (ch + 1 < NC) {
            load_chunk(ch + 1, (ch + 1) & 1);
            asm volatile("cp.async.wait_group 1;" ::: "memory");
        } else {
            asm volatile("cp.async.wait_group 0;" ::: "memory");
        }
        __syncthreads();
        const uint32_t base = sb + (uint32_t)(ch & 1) * 40960;
#pragma unroll
        for (int s = 0; s < 2; s++) {
            uint32_t a[2][2][4];
#pragma unroll
            for (int mf = 0; mf < 2; mf++) {
                LDSM4(a[mf][0], base + aoff + mf * 1280 + s * 32);
                LDSM4(a[mf][1], base + 10240 + aoff + mf * 1280 + s * 32);
            }
#pragma unroll
            for (int np = 0; np < 4; np++) {
                uint32_t bh[4], bl[4];
                LDSM4(bh, base + 20480 + boff + np * 1280 + s * 32);
                LDSM4(bl, base + 30720 + boff + np * 1280 + s * 32);
#pragma unroll
                for (int mf = 0; mf < 2; mf++) {
#pragma unroll
                    for (int h = 0; h < 2; h++) {
                        const int nf = np * 2 + h;
                        MMA_BF16(acc[mf][nf], a[mf][0], bh[2 * h], bh[2 * h + 1]);
                        MMA_BF16(acc[mf][nf], a[mf][0], bl[2 * h], bl[2 * h + 1]);
                        MMA_BF16(acc[mf][nf], a[mf][1], bh[2 * h], bh[2 * h + 1]);
                    }
                }
            }
        }
        __syncthreads();
    }

    // ------------------------------ epilogue ------------------------------
    const int rg = m0 + warp_m * 32 + (lane >> 2);
    const int cg = n0 + warp_n * 64 + (lane & 3) * 2;
    const int mmode = g_mask_mode;

#pragma unroll
    for (int mf = 0; mf < 2; mf++) {
#pragma unroll
        for (int nf = 0; nf < 8; nf++) {
            const int R = rg + mf * 16;
            const int C0 = cg + nf * 8;
            const float v0 = acc[mf][nf][0], v1 = acc[mf][nf][1];
            const float v2 = acc[mf][nf][2], v3 = acc[mf][nf][3];
            if (mode == 0) {
                float r0 = fmaxf(v0, 0.f), r1 = fmaxf(v1, 0.f);
                float r2 = fmaxf(v2, 0.f), r3 = fmaxf(v3, 0.f);
                __nv_bfloat16 h0, l0, h1, l1, h2, l2, h3, l3;
                split2(r0, h0, l0); split2(r1, h1, l1);
                split2(r2, h2, l2); split2(r3, h3, l3);
                uint32_t hp0 = (uint32_t)__bfloat16_as_ushort(h0) | ((uint32_t)__bfloat16_as_ushort(h1) << 16);
                uint32_t lp0 = (uint32_t)__bfloat16_as_ushort(l0) | ((uint32_t)__bfloat16_as_ushort(l1) << 16);
                uint32_t hp1 = (uint32_t)__bfloat16_as_ushort(h2) | ((uint32_t)__bfloat16_as_ushort(h3) << 16);
                uint32_t lp1 = (uint32_t)__bfloat16_as_ushort(l2) | ((uint32_t)__bfloat16_as_ushort(l3) << 16);
                *reinterpret_cast<uint32_t*>(Chi + (size_t)R * ldc + C0) = hp0;
                *reinterpret_cast<uint32_t*>(Clo + (size_t)R * ldc + C0) = lp0;
                *reinterpret_cast<uint32_t*>(Chi + (size_t)(R + 8) * ldc + C0) = hp1;
                *reinterpret_cast<uint32_t*>(Clo + (size_t)(R + 8) * ldc + C0) = lp1;
            } else if (mode == 1) {
                const bool mjA = mask_at(YM, b * 2048 + C0, mmode);
                const bool mjB = mask_at(YM, b * 2048 + C0 + 1, mmode);
                const bool mi0 = mask_at(XM, b * 2048 + R, mmode);
                const bool mi8 = mask_at(XM, b * 2048 + R + 8, mmode);
                float2 w0 = { (mi0 || mjA) ? NEGV : v0, (mi0 || mjB) ? NEGV : v1 };
                float2 w1 = { (mi8 || mjA) ? NEGV : v2, (mi8 || mjB) ? NEGV : v3 };
                *reinterpret_cast<float2*>(C + (size_t)b * sCb + (size_t)R * ldc + C0) = w0;
                *reinterpret_cast<float2*>(C + (size_t)b * sCb + (size_t)(R + 8) * ldc + C0) = w1;
            } else {
                float2 w0 = { v0, v1 };
                float2 w1 = { v2, v3 };
                *reinterpret_cast<float2*>(C + (size_t)b * sCb + (size_t)R * ldc + C0) = w0;
                *reinterpret_cast<float2*>(C + (size_t)b * sCb + (size_t)(R + 8) * ldc + C0) = w1;
            }
        }
    }
}

// =================================================================================
extern "C" void kernel_launch(void* const* d_in, const int* in_sizes, int n_in,
                              void* d_out, int out_size)
{
    (void)in_sizes; (void)n_in; (void)out_size;
    const float* x  = (const float*)d_in[0];
    const float* y  = (const float*)d_in[1];
    const void*  xm = d_in[2];
    const void*  ym = d_in[3];
    const float* Wx = (const float*)d_in[4];
    const float* Wy = (const float*)d_in[5];
    float* out = (float*)d_out;

    static const int SMEM_GEMM = 81920;
    cudaFuncSetAttribute(gemm_hmma_kernel, cudaFuncAttributeMaxDynamicSharedMemorySize, SMEM_GEMM);

    detect_mask_kernel<<<1, 32>>>((const unsigned char*)xm);

    // fp32 -> bf16 hi/lo splits of inputs
    split_plain_kernel<<<32768, 256>>>(x, 0, 33554432);
    split_plain_kernel<<<32768, 256>>>(y, 1, 33554432);
    split_plain_kernel<<<1024, 256>>>(Wx, 2, 1048576);
    split_plain_kernel<<<1024, 256>>>(Wy, 3, 1048576);
    // transposed splits: y^T [d,j], x^T [d,i]
    transpose_split_kernel<<<dim3(32, 64, 16), dim3(32, 8)>>>(y, 0);
    transpose_split_kernel<<<dim3(32, 64, 16), dim3(32, 8)>>>(x, 1);

    // projections (relu + split epilogue)
    gemm_hmma_kernel<<<dim3(8, 256, 1), 256, SMEM_GEMM>>>(0, nullptr, nullptr, nullptr);
    gemm_hmma_kernel<<<dim3(8, 256, 1), 256, SMEM_GEMM>>>(1, nullptr, nullptr, nullptr);
    // scores (masked fp32 epilogue)
    gemm_hmma_kernel<<<dim3(16, 16, 16), 256, SMEM_GEMM>>>(2, nullptr, xm, ym);
    // softmax stats
    row_stats_kernel<<<32768, 256>>>();
    col_stats_kernel<<<dim3(64, 16), dim3(32, 8)>>>();
    // probability splits
    exp_row_kernel<<<65536, 256>>>();
    exp_colT_kernel<<<dim3(64, 64, 16), dim3(32, 8)>>>();
    // attention GEMMs
    gemm_hmma_kernel<<<dim3(8, 16, 16), 256, SMEM_GEMM>>>(3, out, nullptr, nullptr);
    gemm_hmma_kernel<<<dim3(8, 16, 16), 256, SMEM_GEMM>>>(4, out + 33554432, nullptr, nullptr);
}

// round 5
// speedup vs baseline: 2.6238x; 1.5330x over previous
#include <cuda_runtime.h>
#include <cuda_bf16.h>
#include <cstdint>

#define NEGV (-1e30f)

// ============================ scratch (device globals) ============================
static __device__ __nv_bfloat16 g_xhi[33554432], g_xlo[33554432];   // x split [16*2048,1024]
static __device__ __nv_bfloat16 g_yhi[33554432], g_ylo[33554432];   // y split
static __device__ __nv_bfloat16 g_wxhi[1048576], g_wxlo[1048576];   // Wx split [1024,1024]
static __device__ __nv_bfloat16 g_wyhi[1048576], g_wylo[1048576];
static __device__ __nv_bfloat16 g_pxhi[33554432], g_pxlo[33554432]; // relu proj splits
static __device__ __nv_bfloat16 g_pyhi[33554432], g_pylo[33554432];
static __device__ float         g_s[67108864];                      // [16,2048,2048] masked scores
static __device__ __nv_bfloat16 g_Phi[67108864], g_Plo[67108864];   // row-softmax probs [i,j]
static __device__ __nv_bfloat16 g_Pchi[67108864], g_Pclo[67108864]; // col-softmax probs transposed [j,i]
static __device__ __nv_bfloat16 g_yThi[33554432], g_yTlo[33554432]; // y^T [d,j]
static __device__ __nv_bfloat16 g_xThi[33554432], g_xTlo[33554432]; // x^T [d,i]
static __device__ float g_cmax[32768], g_cinv[32768];
static __device__ int   g_mask_mode;

// ============================ helpers =============================================
static __device__ __forceinline__ uint32_t smem_u32(const void* p) {
    uint32_t a;
    asm("{ .reg .u64 t; cvta.to.shared.u64 t, %1; cvt.u32.u64 %0, t; }" : "=r"(a) : "l"(p));
    return a;
}

#define LDSM4(R, A)                                                                   \
    asm volatile("ldmatrix.sync.aligned.m8n8.x4.shared.b16 {%0,%1,%2,%3}, [%4];"      \
        : "=r"((R)[0]), "=r"((R)[1]), "=r"((R)[2]), "=r"((R)[3]) : "r"(A))

#define MMA_BF16(C, A, B0, B1)                                                        \
    asm volatile("mma.sync.aligned.m16n8k16.row.col.f32.bf16.bf16.f32 "               \
        "{%0,%1,%2,%3},{%4,%5,%6,%7},{%8,%9},{%0,%1,%2,%3};"                          \
        : "+f"((C)[0]), "+f"((C)[1]), "+f"((C)[2]), "+f"((C)[3])                      \
        : "r"((A)[0]), "r"((A)[1]), "r"((A)[2]), "r"((A)[3]), "r"(B0), "r"(B1))

__global__ void detect_mask_kernel(const unsigned char* __restrict__ xm) {
    if (threadIdx.x == 0 && blockIdx.x == 0) {
        unsigned int c1 = 0, c3 = 0;
        for (int k = 0; k < 4096; k += 4) { c1 |= xm[k + 1]; c3 |= xm[k + 3]; }
        g_mask_mode = c1 ? 0 : (c3 ? 2 : 1);
    }
}
__device__ __forceinline__ bool mask_at(const void* p, int idx, int mode) {
    if (mode == 0) return ((const unsigned char*)p)[idx] != 0;
    if (mode == 1) return ((const int*)p)[idx] != 0;
    return ((const float*)p)[idx] != 0.0f;
}

__device__ __forceinline__ void split2(float v, __nv_bfloat16& h, __nv_bfloat16& l) {
    h = __float2bfloat16(v);
    l = __float2bfloat16(v - __bfloat162float(h));
}

// ============================ split / transpose kernels ===========================
__global__ void split_plain_kernel(const float* __restrict__ src, int which, int n) {
    __nv_bfloat16 *H, *L;
    if (which == 0)      { H = g_xhi;  L = g_xlo;  }
    else if (which == 1) { H = g_yhi;  L = g_ylo;  }
    else if (which == 2) { H = g_wxhi; L = g_wxlo; }
    else                 { H = g_wyhi; L = g_wylo; }
    int i4 = (blockIdx.x * 256 + threadIdx.x) * 4;
    if (i4 >= n) return;
    float4 v = *reinterpret_cast<const float4*>(src + i4);
    __nv_bfloat16 h0, l0, h1, l1, h2, l2, h3, l3;
    split2(v.x, h0, l0); split2(v.y, h1, l1); split2(v.z, h2, l2); split2(v.w, h3, l3);
    ushort4 Hp = { __bfloat16_as_ushort(h0), __bfloat16_as_ushort(h1),
                   __bfloat16_as_ushort(h2), __bfloat16_as_ushort(h3) };
    ushort4 Lp = { __bfloat16_as_ushort(l0), __bfloat16_as_ushort(l1),
                   __bfloat16_as_ushort(l2), __bfloat16_as_ushort(l3) };
    *reinterpret_cast<ushort4*>(H + i4) = Hp;
    *reinterpret_cast<ushort4*>(L + i4) = Lp;
}

// src [b][2048 r][1024 c] fp32 -> dst [b][1024 c][2048 r] bf16 hi/lo
__global__ void transpose_split_kernel(const float* __restrict__ src, int which) {
    __nv_bfloat16* H = which ? g_xThi : g_yThi;
    __nv_bfloat16* L = which ? g_xTlo : g_yTlo;
    __shared__ float sm[32][33];
    const int b = blockIdx.z;
    const int c0 = blockIdx.x * 32, r0 = blockIdx.y * 32;
    const int tx = threadIdx.x, ty = threadIdx.y;
    const float* S = src + (size_t)b * 2048 * 1024;
#pragma unroll
    for (int k = 0; k < 4; k++) {
        int r = ty * 4 + k;
        sm[r][tx] = S[(size_t)(r0 + r) * 1024 + c0 + tx];
    }
    __syncthreads();
    __nv_bfloat16* Hb = H + (size_t)b * 1024 * 2048;
    __nv_bfloat16* Lb = L + (size_t)b * 1024 * 2048;
#pragma unroll
    for (int k = 0; k < 4; k++) {
        int c = ty * 4 + k;
        float v = sm[tx][c];
        __nv_bfloat16 h, l; split2(v, h, l);
        size_t o = (size_t)(c0 + c) * 2048 + r0 + tx;
        Hb[o] = h; Lb[o] = l;
    }
}

// ============================ fused row softmax (stats + exp + split) =============
__global__ void row_softmax_kernel() {
    const int row = blockIdx.x;
    const float* sp = g_s + (size_t)row * 2048;
    const int t = threadIdx.x;                       // 256 threads, 8 elems each
    float v[8];
    *reinterpret_cast<float4*>(&v[0]) = *reinterpret_cast<const float4*>(sp + t * 8);
    *reinterpret_cast<float4*>(&v[4]) = *reinterpret_cast<const float4*>(sp + t * 8 + 4);
    float m = v[0];
#pragma unroll
    for (int r = 1; r < 8; r++) m = fmaxf(m, v[r]);
    __shared__ float red[256];
    red[t] = m; __syncthreads();
    for (int s = 128; s > 0; s >>= 1) { if (t < s) red[t] = fmaxf(red[t], red[t + s]); __syncthreads(); }
    const float rm = red[0]; __syncthreads();
    float p[8], sum = 0.f;
#pragma unroll
    for (int r = 0; r < 8; r++) { p[r] = __expf(v[r] - rm); sum += p[r]; }
    red[t] = sum; __syncthreads();
    for (int s = 128; s > 0; s >>= 1) { if (t < s) red[t] += red[t + s]; __syncthreads(); }
    const float ri = 1.0f / red[0];
    size_t o = (size_t)row * 2048 + t * 8;
#pragma unroll
    for (int g = 0; g < 2; g++) {
        __nv_bfloat16 h[4], l[4];
#pragma unroll
        for (int q = 0; q < 4; q++) split2(p[g * 4 + q] * ri, h[q], l[q]);
        ushort4 Hp = { __bfloat16_as_ushort(h[0]), __bfloat16_as_ushort(h[1]),
                       __bfloat16_as_ushort(h[2]), __bfloat16_as_ushort(h[3]) };
        ushort4 Lp = { __bfloat16_as_ushort(l[0]), __bfloat16_as_ushort(l[1]),
                       __bfloat16_as_ushort(l[2]), __bfloat16_as_ushort(l[3]) };
        *reinterpret_cast<ushort4*>(g_Phi + o + g * 4) = Hp;
        *reinterpret_cast<ushort4*>(g_Plo + o + g * 4) = Lp;
    }
}

// ============================ col softmax stats ===================================
__global__ void col_stats_kernel() {
    const int b = blockIdx.y;
    const int tx = threadIdx.x, ty = threadIdx.y;
    const int j = blockIdx.x * 32 + tx;
    const float* sp = g_s + (size_t)b * 2048 * 2048 + j;
    float m = -3e38f;
    for (int i = ty; i < 2048; i += 8) m = fmaxf(m, sp[(size_t)i * 2048]);
    __shared__ float red[8][32];
    red[ty][tx] = m; __syncthreads();
    if (ty == 0) {
        float mm = red[0][tx];
#pragma unroll
        for (int r = 1; r < 8; r++) mm = fmaxf(mm, red[r][tx]);
        red[0][tx] = mm;
    }
    __syncthreads();
    const float cm = red[0][tx]; __syncthreads();
    float sum = 0.f;
    for (int i = ty; i < 2048; i += 8) sum += __expf(sp[(size_t)i * 2048] - cm);
    red[ty][tx] = sum; __syncthreads();
    if (ty == 0) {
        float ss = red[0][tx];
#pragma unroll
        for (int r = 1; r < 8; r++) ss += red[r][tx];
        g_cmax[b * 2048 + j] = cm;
        g_cinv[b * 2048 + j] = 1.0f / ss;
    }
}

__global__ void exp_colT_kernel() {
    __shared__ float sm[32][33];
    const int b = blockIdx.z;
    const int i0 = blockIdx.x * 32, j0 = blockIdx.y * 32;
    const int tx = threadIdx.x, ty = threadIdx.y;
    const float* S = g_s + (size_t)b * 2048 * 2048;
    const int j = j0 + tx;
    const float cm = g_cmax[b * 2048 + j], ci = g_cinv[b * 2048 + j];
#pragma unroll
    for (int k = 0; k < 4; k++) {
        int i = ty * 4 + k;
        float v = S[(size_t)(i0 + i) * 2048 + j];
        sm[tx][i] = __expf(v - cm) * ci;
    }
    __syncthreads();
    __nv_bfloat16* Hb = g_Pchi + (size_t)b * 2048 * 2048;
    __nv_bfloat16* Lb = g_Pclo + (size_t)b * 2048 * 2048;
#pragma unroll
    for (int k = 0; k < 4; k++) {
        int jj = ty * 4 + k;
        float v = sm[jj][tx];
        __nv_bfloat16 h, l; split2(v, h, l);
        size_t o = (size_t)(j0 + jj) * 2048 + i0 + tx;
        Hb[o] = h; Lb[o] = l;
    }
}

// ============================ HMMA split GEMM =====================================
// which: 0=proj_x, 1=proj_y, 2=score, 3=attn_row, 4=attn_col
// CTA tile 128x128, 8 warps (4M x 2N), warp tile 32x64, K-chunk 32, double buffer.
// Smem per chunk: 4 tiles (Ahi,Alo,Bhi,Blo), each 128 rows x 80B (64B data + 16B pad).
__global__ __launch_bounds__(256, 2)
void gemm_hmma_kernel(int which, float* __restrict__ Cout,
                      const void* __restrict__ XM, const void* __restrict__ YM)
{
    const __nv_bfloat16 *Ah, *Al, *Bh, *Bl;
    size_t sAb = 0, sBb = 0, sCb = 0;
    int lda, ldb, K, ldc, mode;
    float* C = Cout;
    __nv_bfloat16 *Chi = nullptr, *Clo = nullptr;
    if (which == 0) {
        Ah = g_xhi; Al = g_xlo; Bh = g_wxhi; Bl = g_wxlo;
        lda = 1024; ldb = 1024; K = 1024; ldc = 1024; mode = 0;
        Chi = g_pxhi; Clo = g_pxlo;
    } else if (which == 1) {
        Ah = g_yhi; Al = g_ylo; Bh = g_wyhi; Bl = g_wylo;
        lda = 1024; ldb = 1024; K = 1024; ldc = 1024; mode = 0;
        Chi = g_pyhi; Clo = g_pylo;
    } else if (which == 2) {
        Ah = g_pxhi; Al = g_pxlo; Bh = g_pyhi; Bl = g_pylo;
        sAb = (size_t)2048 * 1024; sBb = (size_t)2048 * 1024; sCb = (size_t)2048 * 2048;
        lda = 1024; ldb = 1024; K = 1024; ldc = 2048; mode = 1;
        C = g_s;
    } else if (which == 3) {
        Ah = g_Phi; Al = g_Plo; Bh = g_yThi; Bl = g_yTlo;
        sAb = (size_t)2048 * 2048; sBb = (size_t)1024 * 2048; sCb = (size_t)2048 * 1024;
        lda = 2048; ldb = 2048; K = 2048; ldc = 1024; mode = 2;
    } else {
        Ah = g_Pchi; Al = g_Pclo; Bh = g_xThi; Bl = g_xTlo;
        sAb = (size_t)2048 * 2048; sBb = (size_t)1024 * 2048; sCb = (size_t)2048 * 1024;
        lda = 2048; ldb = 2048; K = 2048; ldc = 1024; mode = 2;
    }

    extern __shared__ __align__(16) char smem_raw[];
    const uint32_t sb = smem_u32(smem_raw);
    const int tid = threadIdx.x, wid = tid >> 5, lane = tid & 31;
    const int warp_m = wid & 3, warp_n = wid >> 2;
    const int b = blockIdx.z;
    const int m0 = blockIdx.y * 128, n0 = blockIdx.x * 128;

    const __nv_bfloat16* tp[4] = {
        Ah + (size_t)b * sAb + (size_t)m0 * lda,
        Al + (size_t)b * sAb + (size_t)m0 * lda,
        Bh + (size_t)b * sBb + (size_t)n0 * ldb,
        Bl + (size_t)b * sBb + (size_t)n0 * ldb
    };

    float acc[2][8][4];
#pragma unroll
    for (int i = 0; i < 2; i++)
#pragma unroll
        for (int j = 0; j < 8; j++)
#pragma unroll
            for (int q = 0; q < 4; q++) acc[i][j][q] = 0.0f;

    // per-lane ldmatrix offsets (bytes); 80B row pitch is conflict-free (row*5 mod 8 distinct)
    const uint32_t aoff = (uint32_t)(warp_m * 32 + (lane & 7) + ((lane >> 3) & 1) * 8) * 80
                        + ((lane >> 4) & 1) * 16;
    const uint32_t boff = (uint32_t)(warp_n * 64 + (lane & 7) + (lane >> 4) * 8) * 80
                        + ((lane >> 3) & 1) * 16;

    const int NC = K >> 5;

    auto load_chunk = [&](int ch, int buf) {
#pragma unroll
        for (int i = 0; i < 8; i++) {
            const int o = i >> 1;
            const int idx = ((i & 1) << 8) + tid;
            const int row = idx >> 2, gr = idx & 3;
            const __nv_bfloat16* src = tp[o] + (size_t)row * (o < 2 ? lda : ldb) + ch * 32 + gr * 8;
            const uint32_t dst = sb + (uint32_t)buf * 40960 + (uint32_t)o * 10240
                               + (uint32_t)row * 80 + gr * 16;
            asm volatile("cp.async.cg.shared.global [%0], [%1], 16;" :: "r"(dst), "l"(src));
        }
        asm volatile("cp.async.commit_group;");
    };

    load_chunk(0, 0);
    for (int ch = 0; ch < NC; ch++) {
        asm volatile("cp.async.wait_group 0;" ::: "memory");
        __syncthreads();
        if (ch + 1 < NC) load_chunk(ch + 1, (ch + 1) & 1);
        const uint32_t base = sb + (uint32_t)(ch & 1) * 40960;
#pragma unroll
        for (int s = 0; s < 2; s++) {
            uint32_t a[2][2][4];
#pragma unroll
            for (int mf = 0; mf < 2; mf++) {
                LDSM4(a[mf][0], base + aoff + mf * 1280 + s * 32);
                LDSM4(a[mf][1], base + 10240 + aoff + mf * 1280 + s * 32);
            }
            uint32_t bh[2][4], bl[2][4];
            LDSM4(bh[0], base + 20480 + boff + s * 32);
            LDSM4(bl[0], base + 30720 + boff + s * 32);
#pragma unroll
            for (int np = 0; np < 4; np++) {
                const int cur = np & 1;
                if (np < 3) {
                    LDSM4(bh[cur ^ 1], base + 20480 + boff + (np + 1) * 1280 + s * 32);
                    LDSM4(bl[cur ^ 1], base + 30720 + boff + (np + 1) * 1280 + s * 32);
                }
#pragma unroll
                for (int mf = 0; mf < 2; mf++) {
#pragma unroll
                    for (int h = 0; h < 2; h++) {
                        const int nf = np * 2 + h;
                        MMA_BF16(acc[mf][nf], a[mf][0], bh[cur][2 * h], bh[cur][2 * h + 1]);
                        MMA_BF16(acc[mf][nf], a[mf][0], bl[cur][2 * h], bl[cur][2 * h + 1]);
                        MMA_BF16(acc[mf][nf], a[mf][1], bh[cur][2 * h], bh[cur][2 * h + 1]);
                    }
                }
            }
        }
    }

    // ------------------------------ epilogue ------------------------------
    const int rg = m0 + warp_m * 32 + (lane >> 2);
    const int cg = n0 + warp_n * 64 + (lane & 3) * 2;
    const int mmode = g_mask_mode;

#pragma unroll
    for (int mf = 0; mf < 2; mf++) {
#pragma unroll
        for (int nf = 0; nf < 8; nf++) {
            const int R = rg + mf * 16;
            const int C0 = cg + nf * 8;
            const float v0 = acc[mf][nf][0], v1 = acc[mf][nf][1];
            const float v2 = acc[mf][nf][2], v3 = acc[mf][nf][3];
            if (mode == 0) {
                float r0 = fmaxf(v0, 0.f), r1 = fmaxf(v1, 0.f);
                float r2 = fmaxf(v2, 0.f), r3 = fmaxf(v3, 0.f);
                __nv_bfloat16 h0, l0, h1, l1, h2, l2, h3, l3;
                split2(r0, h0, l0); split2(r1, h1, l1);
                split2(r2, h2, l2); split2(r3, h3, l3);
                uint32_t hp0 = (uint32_t)__bfloat16_as_ushort(h0) | ((uint32_t)__bfloat16_as_ushort(h1) << 16);
                uint32_t lp0 = (uint32_t)__bfloat16_as_ushort(l0) | ((uint32_t)__bfloat16_as_ushort(l1) << 16);
                uint32_t hp1 = (uint32_t)__bfloat16_as_ushort(h2) | ((uint32_t)__bfloat16_as_ushort(h3) << 16);
                uint32_t lp1 = (uint32_t)__bfloat16_as_ushort(l2) | ((uint32_t)__bfloat16_as_ushort(l3) << 16);
                *reinterpret_cast<uint32_t*>(Chi + (size_t)R * ldc + C0) = hp0;
                *reinterpret_cast<uint32_t*>(Clo + (size_t)R * ldc + C0) = lp0;
                *reinterpret_cast<uint32_t*>(Chi + (size_t)(R + 8) * ldc + C0) = hp1;
                *reinterpret_cast<uint32_t*>(Clo + (size_t)(R + 8) * ldc + C0) = lp1;
            } else if (mode == 1) {
                const bool mjA = mask_at(YM, b * 2048 + C0, mmode);
                const bool mjB = mask_at(YM, b * 2048 + C0 + 1, mmode);
                const bool mi0 = mask_at(XM, b * 2048 + R, mmode);
                const bool mi8 = mask_at(XM, b * 2048 + R + 8, mmode);
                float2 w0 = { (mi0 || mjA) ? NEGV : v0, (mi0 || mjB) ? NEGV : v1 };
                float2 w1 = { (mi8 || mjA) ? NEGV : v2, (mi8 || mjB) ? NEGV : v3 };
                *reinterpret_cast<float2*>(C + (size_t)b * sCb + (size_t)R * ldc + C0) = w0;
                *reinterpret_cast<float2*>(C + (size_t)b * sCb + (size_t)(R + 8) * ldc + C0) = w1;
            } else {
                float2 w0 = { v0, v1 };
                float2 w1 = { v2, v3 };
                *reinterpret_cast<float2*>(C + (size_t)b * sCb + (size_t)R * ldc + C0) = w0;
                *reinterpret_cast<float2*>(C + (size_t)b * sCb + (size_t)(R + 8) * ldc + C0) = w1;
            }
        }
    }
}

// =================================================================================
extern "C" void kernel_launch(void* const* d_in, const int* in_sizes, int n_in,
                              void* d_out, int out_size)
{
    (void)in_sizes; (void)n_in; (void)out_size;
    const float* x  = (const float*)d_in[0];
    const float* y  = (const float*)d_in[1];
    const void*  xm = d_in[2];
    const void*  ym = d_in[3];
    const float* Wx = (const float*)d_in[4];
    const float* Wy = (const float*)d_in[5];
    float* out = (float*)d_out;

    static const int SMEM_GEMM = 81920;
    cudaFuncSetAttribute(gemm_hmma_kernel, cudaFuncAttributeMaxDynamicSharedMemorySize, SMEM_GEMM);

    // launches 0-4 (so launch #5 = proj GEMM gets captured by ncu -s 5 -c 1)
    detect_mask_kernel<<<1, 32>>>((const unsigned char*)xm);
    split_plain_kernel<<<32768, 256>>>(x, 0, 33554432);
    split_plain_kernel<<<32768, 256>>>(y, 1, 33554432);
    split_plain_kernel<<<1024, 256>>>(Wx, 2, 1048576);
    split_plain_kernel<<<1024, 256>>>(Wy, 3, 1048576);

    // projections (relu + split epilogue) — launch #5 is a GEMM now
    gemm_hmma_kernel<<<dim3(8, 256, 1), 256, SMEM_GEMM>>>(0, nullptr, nullptr, nullptr);
    gemm_hmma_kernel<<<dim3(8, 256, 1), 256, SMEM_GEMM>>>(1, nullptr, nullptr, nullptr);

    // transposed splits: y^T [d,j], x^T [d,i] (independent of projections)
    transpose_split_kernel<<<dim3(32, 64, 16), dim3(32, 8)>>>(y, 0);
    transpose_split_kernel<<<dim3(32, 64, 16), dim3(32, 8)>>>(x, 1);

    // scores (masked fp32 epilogue)
    gemm_hmma_kernel<<<dim3(16, 16, 16), 256, SMEM_GEMM>>>(2, nullptr, xm, ym);
    // softmax: fused row pass; col stats + transpose-exp
    row_softmax_kernel<<<32768, 256>>>();
    col_stats_kernel<<<dim3(64, 16), dim3(32, 8)>>>();
    exp_colT_kernel<<<dim3(64, 64, 16), dim3(32, 8)>>>();
    // attention GEMMs
    gemm_hmma_kernel<<<dim3(8, 16, 16), 256, SMEM_GEMM>>>(3, out, nullptr, nullptr);
    gemm_hmma_kernel<<<dim3(8, 16, 16), 256, SMEM_GEMM>>>(4, out + 33554432, nullptr, nullptr);
}

// round 6
// speedup vs baseline: 2.7545x; 1.0498x over previous
#include <cuda_runtime.h>
#include <cuda_bf16.h>
#include <cstdint>

#define NEGV (-1e30f)

// ============================ scratch (device globals) ============================
static __device__ __nv_bfloat16 g_xhi[33554432], g_xlo[33554432];   // x split [16*2048,1024]
static __device__ __nv_bfloat16 g_yhi[33554432], g_ylo[33554432];   // y split
static __device__ __nv_bfloat16 g_wxhi[1048576], g_wxlo[1048576];   // Wx split [1024,1024]
static __device__ __nv_bfloat16 g_wyhi[1048576], g_wylo[1048576];
static __device__ __nv_bfloat16 g_pxhi[33554432], g_pxlo[33554432]; // relu proj splits
static __device__ __nv_bfloat16 g_pyhi[33554432], g_pylo[33554432];
static __device__ float         g_s[67108864];                      // [16,2048,2048] masked scores
static __device__ __nv_bfloat16 g_Phi[67108864], g_Plo[67108864];   // row-softmax probs [i,j]
static __device__ __nv_bfloat16 g_Pchi[67108864], g_Pclo[67108864]; // col-softmax probs transposed [j,i]
static __device__ __nv_bfloat16 g_yThi[33554432], g_yTlo[33554432]; // y^T [d,j]
static __device__ __nv_bfloat16 g_xThi[33554432], g_xTlo[33554432]; // x^T [d,i]
static __device__ float g_cmax[32768], g_cinv[32768];
static __device__ int   g_mask_mode;

// ============================ helpers =============================================
static __device__ __forceinline__ uint32_t smem_u32(const void* p) {
    uint32_t a;
    asm("{ .reg .u64 t; cvta.to.shared.u64 t, %1; cvt.u32.u64 %0, t; }" : "=r"(a) : "l"(p));
    return a;
}

#define LDSM4(R, A)                                                                   \
    asm volatile("ldmatrix.sync.aligned.m8n8.x4.shared.b16 {%0,%1,%2,%3}, [%4];"      \
        : "=r"((R)[0]), "=r"((R)[1]), "=r"((R)[2]), "=r"((R)[3]) : "r"(A))

#define MMA_BF16(C, A, B0, B1)                                                        \
    asm volatile("mma.sync.aligned.m16n8k16.row.col.f32.bf16.bf16.f32 "               \
        "{%0,%1,%2,%3},{%4,%5,%6,%7},{%8,%9},{%0,%1,%2,%3};"                          \
        : "+f"((C)[0]), "+f"((C)[1]), "+f"((C)[2]), "+f"((C)[3])                      \
        : "r"((A)[0]), "r"((A)[1]), "r"((A)[2]), "r"((A)[3]), "r"(B0), "r"(B1))

__global__ void detect_mask_kernel(const unsigned char* __restrict__ xm) {
    if (threadIdx.x == 0 && blockIdx.x == 0) {
        unsigned int c1 = 0, c3 = 0;
        for (int k = 0; k < 4096; k += 4) { c1 |= xm[k + 1]; c3 |= xm[k + 3]; }
        g_mask_mode = c1 ? 0 : (c3 ? 2 : 1);
    }
}
__device__ __forceinline__ bool mask_at(const void* p, int idx, int mode) {
    if (mode == 0) return ((const unsigned char*)p)[idx] != 0;
    if (mode == 1) return ((const int*)p)[idx] != 0;
    return ((const float*)p)[idx] != 0.0f;
}

__device__ __forceinline__ void split2(float v, __nv_bfloat16& h, __nv_bfloat16& l) {
    h = __float2bfloat16(v);
    l = __float2bfloat16(v - __bfloat162float(h));
}

// ============================ weight split kernel =================================
__global__ void split_plain_kernel(const float* __restrict__ src, int which, int n) {
    __nv_bfloat16 *H, *L;
    if (which == 2) { H = g_wxhi; L = g_wxlo; }
    else            { H = g_wyhi; L = g_wylo; }
    int i4 = (blockIdx.x * 256 + threadIdx.x) * 4;
    if (i4 >= n) return;
    float4 v = *reinterpret_cast<const float4*>(src + i4);
    __nv_bfloat16 h0, l0, h1, l1, h2, l2, h3, l3;
    split2(v.x, h0, l0); split2(v.y, h1, l1); split2(v.z, h2, l2); split2(v.w, h3, l3);
    ushort4 Hp = { __bfloat16_as_ushort(h0), __bfloat16_as_ushort(h1),
                   __bfloat16_as_ushort(h2), __bfloat16_as_ushort(h3) };
    ushort4 Lp = { __bfloat16_as_ushort(l0), __bfloat16_as_ushort(l1),
                   __bfloat16_as_ushort(l2), __bfloat16_as_ushort(l3) };
    *reinterpret_cast<ushort4*>(H + i4) = Hp;
    *reinterpret_cast<ushort4*>(L + i4) = Lp;
}

// ============ fused split + transpose: one fp32 read, both layouts out ============
// src [b][2048 r][1024 c] fp32 -> H/L [b*2048+r][c], HT/LT [b][c][r]
// tile 64x64, 256 threads. which: 0 = y, 1 = x.
__global__ void split_both_kernel(const float* __restrict__ src, int which) {
    __nv_bfloat16* H  = which ? g_xhi  : g_yhi;
    __nv_bfloat16* L  = which ? g_xlo  : g_ylo;
    __nv_bfloat16* HT = which ? g_xThi : g_yThi;
    __nv_bfloat16* LT = which ? g_xTlo : g_yTlo;
    __shared__ float sm[64][65];
    const int b = blockIdx.z;
    const int r0 = blockIdx.y * 64, c0 = blockIdx.x * 64;
    const int t = threadIdx.x;
    const float* S = src + (size_t)b * 2048 * 1024;
#pragma unroll
    for (int k = 0; k < 16; k++) {
        int idx = k * 256 + t;
        int r = idx >> 6, c = idx & 63;
        sm[r][c] = S[(size_t)(r0 + r) * 1024 + c0 + c];
    }
    __syncthreads();
    // row-major split out
    __nv_bfloat16* Hb = H + (size_t)b * 2048 * 1024;
    __nv_bfloat16* Lb = L + (size_t)b * 2048 * 1024;
#pragma unroll
    for (int k = 0; k < 4; k++) {
        int idx = k * 1024 + t * 4;
        int r = idx >> 6, c = idx & 63;
        __nv_bfloat16 h[4], l[4];
#pragma unroll
        for (int q = 0; q < 4; q++) split2(sm[r][c + q], h[q], l[q]);
        ushort4 Hp = { __bfloat16_as_ushort(h[0]), __bfloat16_as_ushort(h[1]),
                       __bfloat16_as_ushort(h[2]), __bfloat16_as_ushort(h[3]) };
        ushort4 Lp = { __bfloat16_as_ushort(l[0]), __bfloat16_as_ushort(l[1]),
                       __bfloat16_as_ushort(l[2]), __bfloat16_as_ushort(l[3]) };
        size_t o = (size_t)(r0 + r) * 1024 + c0 + c;
        *reinterpret_cast<ushort4*>(Hb + o) = Hp;
        *reinterpret_cast<ushort4*>(Lb + o) = Lp;
    }
    // transposed split out
    __nv_bfloat16* HTb = HT + (size_t)b * 1024 * 2048;
    __nv_bfloat16* LTb = LT + (size_t)b * 1024 * 2048;
#pragma unroll
    for (int k = 0; k < 4; k++) {
        int idx = k * 1024 + t * 4;
        int c = idx >> 6, r = idx & 63;
        __nv_bfloat16 h[4], l[4];
#pragma unroll
        for (int q = 0; q < 4; q++) split2(sm[r + q][c], h[q], l[q]);
        ushort4 Hp = { __bfloat16_as_ushort(h[0]), __bfloat16_as_ushort(h[1]),
                       __bfloat16_as_ushort(h[2]), __bfloat16_as_ushort(h[3]) };
        ushort4 Lp = { __bfloat16_as_ushort(l[0]), __bfloat16_as_ushort(l[1]),
                       __bfloat16_as_ushort(l[2]), __bfloat16_as_ushort(l[3]) };
        size_t o = (size_t)(c0 + c) * 2048 + r0 + r;
        *reinterpret_cast<ushort4*>(HTb + o) = Hp;
        *reinterpret_cast<ushort4*>(LTb + o) = Lp;
    }
}

// ============================ fused row softmax (stats + exp + split) =============
__global__ void row_softmax_kernel() {
    const int row = blockIdx.x;
    const float* sp = g_s + (size_t)row * 2048;
    const int t = threadIdx.x;                       // 256 threads, 8 elems each
    float v[8];
    *reinterpret_cast<float4*>(&v[0]) = *reinterpret_cast<const float4*>(sp + t * 8);
    *reinterpret_cast<float4*>(&v[4]) = *reinterpret_cast<const float4*>(sp + t * 8 + 4);
    float m = v[0];
#pragma unroll
    for (int r = 1; r < 8; r++) m = fmaxf(m, v[r]);
    __shared__ float red[256];
    red[t] = m; __syncthreads();
    for (int s = 128; s > 0; s >>= 1) { if (t < s) red[t] = fmaxf(red[t], red[t + s]); __syncthreads(); }
    const float rm = red[0]; __syncthreads();
    float p[8], sum = 0.f;
#pragma unroll
    for (int r = 0; r < 8; r++) { p[r] = __expf(v[r] - rm); sum += p[r]; }
    red[t] = sum; __syncthreads();
    for (int s = 128; s > 0; s >>= 1) { if (t < s) red[t] += red[t + s]; __syncthreads(); }
    const float ri = 1.0f / red[0];
    size_t o = (size_t)row * 2048 + t * 8;
#pragma unroll
    for (int g = 0; g < 2; g++) {
        __nv_bfloat16 h[4], l[4];
#pragma unroll
        for (int q = 0; q < 4; q++) split2(p[g * 4 + q] * ri, h[q], l[q]);
        ushort4 Hp = { __bfloat16_as_ushort(h[0]), __bfloat16_as_ushort(h[1]),
                       __bfloat16_as_ushort(h[2]), __bfloat16_as_ushort(h[3]) };
        ushort4 Lp = { __bfloat16_as_ushort(l[0]), __bfloat16_as_ushort(l[1]),
                       __bfloat16_as_ushort(l[2]), __bfloat16_as_ushort(l[3]) };
        *reinterpret_cast<ushort4*>(g_Phi + o + g * 4) = Hp;
        *reinterpret_cast<ushort4*>(g_Plo + o + g * 4) = Lp;
    }
}

// ============================ col softmax stats ===================================
__global__ void col_stats_kernel() {
    const int b = blockIdx.y;
    const int tx = threadIdx.x, ty = threadIdx.y;
    const int j = blockIdx.x * 32 + tx;
    const float* sp = g_s + (size_t)b * 2048 * 2048 + j;
    float m = -3e38f;
    for (int i = ty; i < 2048; i += 8) m = fmaxf(m, sp[(size_t)i * 2048]);
    __shared__ float red[8][32];
    red[ty][tx] = m; __syncthreads();
    if (ty == 0) {
        float mm = red[0][tx];
#pragma unroll
        for (int r = 1; r < 8; r++) mm = fmaxf(mm, red[r][tx]);
        red[0][tx] = mm;
    }
    __syncthreads();
    const float cm = red[0][tx]; __syncthreads();
    float sum = 0.f;
    for (int i = ty; i < 2048; i += 8) sum += __expf(sp[(size_t)i * 2048] - cm);
    red[ty][tx] = sum; __syncthreads();
    if (ty == 0) {
        float ss = red[0][tx];
#pragma unroll
        for (int r = 1; r < 8; r++) ss += red[r][tx];
        g_cmax[b * 2048 + j] = cm;
        g_cinv[b * 2048 + j] = 1.0f / ss;
    }
}

__global__ void exp_colT_kernel() {
    __shared__ float sm[32][33];
    const int b = blockIdx.z;
    const int i0 = blockIdx.x * 32, j0 = blockIdx.y * 32;
    const int tx = threadIdx.x, ty = threadIdx.y;
    const float* S = g_s + (size_t)b * 2048 * 2048;
    const int j = j0 + tx;
    const float cm = g_cmax[b * 2048 + j], ci = g_cinv[b * 2048 + j];
#pragma unroll
    for (int k = 0; k < 4; k++) {
        int i = ty * 4 + k;
        float v = S[(size_t)(i0 + i) * 2048 + j];
        sm[tx][i] = __expf(v - cm) * ci;
    }
    __syncthreads();
    __nv_bfloat16* Hb = g_Pchi + (size_t)b * 2048 * 2048;
    __nv_bfloat16* Lb = g_Pclo + (size_t)b * 2048 * 2048;
#pragma unroll
    for (int k = 0; k < 4; k++) {
        int jj = ty * 4 + k;
        float v = sm[jj][tx];
        __nv_bfloat16 h, l; split2(v, h, l);
        size_t o = (size_t)(j0 + jj) * 2048 + i0 + tx;
        Hb[o] = h; Lb[o] = l;
    }
}

// ============================ HMMA split GEMM =====================================
// which: 0=proj_x, 1=proj_y, 2=score, 3=attn_row, 4=attn_col
__global__ __launch_bounds__(256, 2)
void gemm_hmma_kernel(int which, float* __restrict__ Cout,
                      const void* __restrict__ XM, const void* __restrict__ YM)
{
    const __nv_bfloat16 *Ah, *Al, *Bh, *Bl;
    size_t sAb = 0, sBb = 0, sCb = 0;
    int lda, ldb, K, ldc, mode;
    float* C = Cout;
    __nv_bfloat16 *Chi = nullptr, *Clo = nullptr;
    if (which == 0) {
        Ah = g_xhi; Al = g_xlo; Bh = g_wxhi; Bl = g_wxlo;
        lda = 1024; ldb = 1024; K = 1024; ldc = 1024; mode = 0;
        Chi = g_pxhi; Clo = g_pxlo;
    } else if (which == 1) {
        Ah = g_yhi; Al = g_ylo; Bh = g_wyhi; Bl = g_wylo;
        lda = 1024; ldb = 1024; K = 1024; ldc = 1024; mode = 0;
        Chi = g_pyhi; Clo = g_pylo;
    } else if (which == 2) {
        Ah = g_pxhi; Al = g_pxlo; Bh = g_pyhi; Bl = g_pylo;
        sAb = (size_t)2048 * 1024; sBb = (size_t)2048 * 1024; sCb = (size_t)2048 * 2048;
        lda = 1024; ldb = 1024; K = 1024; ldc = 2048; mode = 1;
        C = g_s;
    } else if (which == 3) {
        Ah = g_Phi; Al = g_Plo; Bh = g_yThi; Bl = g_yTlo;
        sAb = (size_t)2048 * 2048; sBb = (size_t)1024 * 2048; sCb = (size_t)2048 * 1024;
        lda = 2048; ldb = 2048; K = 2048; ldc = 1024; mode = 2;
    } else {
        Ah = g_Pchi; Al = g_Pclo; Bh = g_xThi; Bl = g_xTlo;
        sAb = (size_t)2048 * 2048; sBb = (size_t)1024 * 2048; sCb = (size_t)2048 * 1024;
        lda = 2048; ldb = 2048; K = 2048; ldc = 1024; mode = 2;
    }

    extern __shared__ __align__(16) char smem_raw[];
    const uint32_t sb = smem_u32(smem_raw);
    const int tid = threadIdx.x, wid = tid >> 5, lane = tid & 31;
    const int warp_m = wid & 3, warp_n = wid >> 2;
    const int b = blockIdx.z;
    const int m0 = blockIdx.y * 128, n0 = blockIdx.x * 128;

    const __nv_bfloat16* tp[4] = {
        Ah + (size_t)b * sAb + (size_t)m0 * lda,
        Al + (size_t)b * sAb + (size_t)m0 * lda,
        Bh + (size_t)b * sBb + (size_t)n0 * ldb,
        Bl + (size_t)b * sBb + (size_t)n0 * ldb
    };

    float acc[2][8][4];
#pragma unroll
    for (int i = 0; i < 2; i++)
#pragma unroll
        for (int j = 0; j < 8; j++)
#pragma unroll
            for (int q = 0; q < 4; q++) acc[i][j][q] = 0.0f;

    // per-lane ldmatrix offsets (bytes); 80B row pitch is conflict-free
    const uint32_t aoff = (uint32_t)(warp_m * 32 + (lane & 7) + ((lane >> 3) & 1) * 8) * 80
                        + ((lane >> 4) & 1) * 16;
    const uint32_t boff = (uint32_t)(warp_n * 64 + (lane & 7) + (lane >> 4) * 8) * 80
                        + ((lane >> 3) & 1) * 16;

    const int NC = K >> 5;

    auto load_chunk = [&](int ch, int buf) {
#pragma unroll
        for (int i = 0; i < 8; i++) {
            const int o = i >> 1;
            const int idx = ((i & 1) << 8) + tid;
            const int row = idx >> 2, gr = idx & 3;
            const __nv_bfloat16* src = tp[o] + (size_t)row * (o < 2 ? lda : ldb) + ch * 32 + gr * 8;
            const uint32_t dst = sb + (uint32_t)buf * 40960 + (uint32_t)o * 10240
                               + (uint32_t)row * 80 + gr * 16;
            asm volatile("cp.async.cg.shared.global [%0], [%1], 16;" :: "r"(dst), "l"(src));
        }
        asm volatile("cp.async.commit_group;");
    };

    load_chunk(0, 0);
    for (int ch = 0; ch < NC; ch++) {
        __syncthreads();                                  // all warps done with buf (ch+1)&1
        if (ch + 1 < NC) {
            load_chunk(ch + 1, (ch + 1) & 1);
            asm volatile("cp.async.wait_group 1;" ::: "memory");   // chunk ch landed
        } else {
            asm volatile("cp.async.wait_group 0;" ::: "memory");
        }
        __syncthreads();                                  // ch's data visible to all warps
        const uint32_t base = sb + (uint32_t)(ch & 1) * 40960;
#pragma unroll
        for (int s = 0; s < 2; s++) {
            uint32_t a[2][2][4];
#pragma unroll
            for (int mf = 0; mf < 2; mf++) {
                LDSM4(a[mf][0], base + aoff + mf * 1280 + s * 32);
                LDSM4(a[mf][1], base + 10240 + aoff + mf * 1280 + s * 32);
            }
            uint32_t bh[2][4], bl[2][4];
            LDSM4(bh[0], base + 20480 + boff + s * 32);
            LDSM4(bl[0], base + 30720 + boff + s * 32);
#pragma unroll
            for (int np = 0; np < 4; np++) {
                const int cur = np & 1;
                if (np < 3) {
                    LDSM4(bh[cur ^ 1], base + 20480 + boff + (np + 1) * 1280 + s * 32);
                    LDSM4(bl[cur ^ 1], base + 30720 + boff + (np + 1) * 1280 + s * 32);
                }
#pragma unroll
                for (int mf = 0; mf < 2; mf++) {
#pragma unroll
                    for (int h = 0; h < 2; h++) {
                        const int nf = np * 2 + h;
                        MMA_BF16(acc[mf][nf], a[mf][0], bh[cur][2 * h], bh[cur][2 * h + 1]);
                        MMA_BF16(acc[mf][nf], a[mf][0], bl[cur][2 * h], bl[cur][2 * h + 1]);
                        MMA_BF16(acc[mf][nf], a[mf][1], bh[cur][2 * h], bh[cur][2 * h + 1]);
                    }
                }
            }
        }
    }

    // ------------------------------ epilogue ------------------------------
    const int rg = m0 + warp_m * 32 + (lane >> 2);
    const int cg = n0 + warp_n * 64 + (lane & 3) * 2;
    const int mmode = g_mask_mode;

#pragma unroll
    for (int mf = 0; mf < 2; mf++) {
#pragma unroll
        for (int nf = 0; nf < 8; nf++) {
            const int R = rg + mf * 16;
            const int C0 = cg + nf * 8;
            const float v0 = acc[mf][nf][0], v1 = acc[mf][nf][1];
            const float v2 = acc[mf][nf][2], v3 = acc[mf][nf][3];
            if (mode == 0) {
                float r0 = fmaxf(v0, 0.f), r1 = fmaxf(v1, 0.f);
                float r2 = fmaxf(v2, 0.f), r3 = fmaxf(v3, 0.f);
                __nv_bfloat16 h0, l0, h1, l1, h2, l2, h3, l3;
                split2(r0, h0, l0); split2(r1, h1, l1);
                split2(r2, h2, l2); split2(r3, h3, l3);
                uint32_t hp0 = (uint32_t)__bfloat16_as_ushort(h0) | ((uint32_t)__bfloat16_as_ushort(h1) << 16);
                uint32_t lp0 = (uint32_t)__bfloat16_as_ushort(l0) | ((uint32_t)__bfloat16_as_ushort(l1) << 16);
                uint32_t hp1 = (uint32_t)__bfloat16_as_ushort(h2) | ((uint32_t)__bfloat16_as_ushort(h3) << 16);
                uint32_t lp1 = (uint32_t)__bfloat16_as_ushort(l2) | ((uint32_t)__bfloat16_as_ushort(l3) << 16);
                *reinterpret_cast<uint32_t*>(Chi + (size_t)R * ldc + C0) = hp0;
                *reinterpret_cast<uint32_t*>(Clo + (size_t)R * ldc + C0) = lp0;
                *reinterpret_cast<uint32_t*>(Chi + (size_t)(R + 8) * ldc + C0) = hp1;
                *reinterpret_cast<uint32_t*>(Clo + (size_t)(R + 8) * ldc + C0) = lp1;
            } else if (mode == 1) {
                const bool mjA = mask_at(YM, b * 2048 + C0, mmode);
                const bool mjB = mask_at(YM, b * 2048 + C0 + 1, mmode);
                const bool mi0 = mask_at(XM, b * 2048 + R, mmode);
                const bool mi8 = mask_at(XM, b * 2048 + R + 8, mmode);
                float2 w0 = { (mi0 || mjA) ? NEGV : v0, (mi0 || mjB) ? NEGV : v1 };
                float2 w1 = { (mi8 || mjA) ? NEGV : v2, (mi8 || mjB) ? NEGV : v3 };
                *reinterpret_cast<float2*>(C + (size_t)b * sCb + (size_t)R * ldc + C0) = w0;
                *reinterpret_cast<float2*>(C + (size_t)b * sCb + (size_t)(R + 8) * ldc + C0) = w1;
            } else {
                float2 w0 = { v0, v1 };
                float2 w1 = { v2, v3 };
                *reinterpret_cast<float2*>(C + (size_t)b * sCb + (size_t)R * ldc + C0) = w0;
                *reinterpret_cast<float2*>(C + (size_t)b * sCb + (size_t)(R + 8) * ldc + C0) = w1;
            }
        }
    }
}

// =================================================================================
extern "C" void kernel_launch(void* const* d_in, const int* in_sizes, int n_in,
                              void* d_out, int out_size)
{
    (void)in_sizes; (void)n_in; (void)out_size;
    const float* x  = (const float*)d_in[0];
    const float* y  = (const float*)d_in[1];
    const void*  xm = d_in[2];
    const void*  ym = d_in[3];
    const float* Wx = (const float*)d_in[4];
    const float* Wy = (const float*)d_in[5];
    float* out = (float*)d_out;

    static const int SMEM_GEMM = 81920;
    cudaFuncSetAttribute(gemm_hmma_kernel, cudaFuncAttributeMaxDynamicSharedMemorySize, SMEM_GEMM);

    // index 0-3
    detect_mask_kernel<<<1, 32>>>((const unsigned char*)xm);
    split_plain_kernel<<<1024, 256>>>(Wx, 2, 1048576);
    split_plain_kernel<<<1024, 256>>>(Wy, 3, 1048576);
    split_both_kernel<<<dim3(16, 32, 16), 256>>>(x, 1);
    // index 4: proj_x GEMM — target of ncu capture
    gemm_hmma_kernel<<<dim3(8, 256, 1), 256, SMEM_GEMM>>>(0, nullptr, nullptr, nullptr);
    // index 5-6
    split_both_kernel<<<dim3(16, 32, 16), 256>>>(y, 0);
    gemm_hmma_kernel<<<dim3(8, 256, 1), 256, SMEM_GEMM>>>(1, nullptr, nullptr, nullptr);
    // scores (masked fp32 epilogue)
    gemm_hmma_kernel<<<dim3(16, 16, 16), 256, SMEM_GEMM>>>(2, nullptr, xm, ym);
    // softmax: fused row pass; col stats + transpose-exp
    row_softmax_kernel<<<32768, 256>>>();
    col_stats_kernel<<<dim3(64, 16), dim3(32, 8)>>>();
    exp_colT_kernel<<<dim3(64, 64, 16), dim3(32, 8)>>>();
    // attention GEMMs
    gemm_hmma_kernel<<<dim3(8, 16, 16), 256, SMEM_GEMM>>>(3, out, nullptr, nullptr);
    gemm_hmma_kernel<<<dim3(8, 16, 16), 256, SMEM_GEMM>>>(4, out + 33554432, nullptr, nullptr);
}